// round 12
// baseline (speedup 1.0000x reference)
#include <cuda_runtime.h>
#include <cuda_fp16.h>
#include <cstdint>

#define NROWS 200000
#define NPAD  200064   /* 1563 * 128 */
#define CDIM  128
#define EPS   1e-5f

__device__ __half g_featH[(long)NROWS * CDIM];
__device__ __half g_WH[9 * CDIM * CDIM];
__device__ __half g_scratchH[3L * NPAD * CDIM];
__device__ float  g_sum[3 * CDIM];
__device__ float  g_sumsq[3 * CDIM];
__device__ float  g_scale[3 * CDIM];
__device__ float  g_shift[3 * CDIM];

__device__ __forceinline__ uint32_t smem_u32(const void* p) {
    uint32_t a;
    asm("{ .reg .u64 t; cvta.to.shared.u64 t, %1; cvt.u32.u64 %0, t; }" : "=r"(a) : "l"(p));
    return a;
}

#define CP_ASYNC16(dst, src, sz) \
    asm volatile("cp.async.cg.shared.global [%0], [%1], 16, %2;" \
                 :: "r"(dst), "l"(src), "r"(sz) : "memory")
#define CP_COMMIT()  asm volatile("cp.async.commit_group;" ::: "memory")
#define CP_WAIT1()   asm volatile("cp.async.wait_group 1;" ::: "memory")

#define LDSM_X4(r, addr) \
    asm volatile("ldmatrix.sync.aligned.m8n8.x4.shared.b16 {%0,%1,%2,%3}, [%4];" \
                 : "=r"((r)[0]), "=r"((r)[1]), "=r"((r)[2]), "=r"((r)[3]) : "r"(addr))
#define LDSM_X4_T(r, addr) \
    asm volatile("ldmatrix.sync.aligned.m8n8.x4.trans.shared.b16 {%0,%1,%2,%3}, [%4];" \
                 : "=r"((r)[0]), "=r"((r)[1]), "=r"((r)[2]), "=r"((r)[3]) : "r"(addr))

#define MMA_F16(c, au, bu)                                                      \
    asm volatile("mma.sync.aligned.m16n8k16.row.col.f32.f16.f16.f32 "           \
        "{%0,%1,%2,%3}, {%4,%5,%6,%7}, {%8,%9}, {%0,%1,%2,%3};"                 \
        : "+f"((c)[0]), "+f"((c)[1]), "+f"((c)[2]), "+f"((c)[3])                \
        : "r"((au)[0]), "r"((au)[1]), "r"((au)[2]), "r"((au)[3]),               \
          "r"((bu)[0]), "r"((bu)[1]))

// fp16 SMEM tiles per stage: A [128 rows x 32 k] = 64 B/row (4 x 16B chunks,
// chunk ^= (row>>1)&3). B [32 k x 128 n] = 256 B/row (16 chunks, chunk ^= k&7).
#define A_TILE    8192u
#define B_TILE    8192u
#define BUF_SZ    16384u
#define SMEM_DYN  32768u   /* 2 buffers */

__global__ void zero_stats_kernel() {
    int t = blockIdx.x * blockDim.x + threadIdx.x;
    if (t < 3 * CDIM) { g_sum[t] = 0.f; g_sumsq[t] = 0.f; }
}

// fp32 -> fp16 copies: features and W (once per launch)
__global__ __launch_bounds__(256)
void convert_feat_kernel(const float* __restrict__ feat)
{
    long tid = (long)blockIdx.x * blockDim.x + threadIdx.x;   // 8 floats each
    long base = tid * 8;
    if (base >= (long)NROWS * CDIM) return;
    float4 v0 = *(const float4*)(feat + base);
    float4 v1 = *(const float4*)(feat + base + 4);
    __half2 h[4];
    h[0] = __floats2half2_rn(v0.x, v0.y);
    h[1] = __floats2half2_rn(v0.z, v0.w);
    h[2] = __floats2half2_rn(v1.x, v1.y);
    h[3] = __floats2half2_rn(v1.z, v1.w);
    *(uint4*)(g_featH + base) = *(uint4*)h;
}

__global__ __launch_bounds__(256)
void convert_w_kernel(const float* __restrict__ W)
{
    long tid = (long)blockIdx.x * blockDim.x + threadIdx.x;   // 8 floats each
    long base = tid * 8;
    if (base >= 9L * CDIM * CDIM) return;
    float4 v0 = *(const float4*)(W + base);
    float4 v1 = *(const float4*)(W + base + 4);
    __half2 h[4];
    h[0] = __floats2half2_rn(v0.x, v0.y);
    h[1] = __floats2half2_rn(v0.z, v0.w);
    h[2] = __floats2half2_rn(v1.x, v1.y);
    h[3] = __floats2half2_rn(v1.z, v1.w);
    *(uint4*)(g_WH + base) = *(uint4*)h;
}

// One CTA: 128-row x 128-col tile of out_a for axis a = blockIdx.y.
// 8 warps: wm = wid&1 (two 64-row bands), wn = wid>>1 (four 32-col bands).
// Warp tile 64x32 = 4x4 mma(m16n8k16) tiles, fp16 in, fp32 accumulate.
// Producer: cp.async.cg (L1-bypass, L2 -> swizzled fp16 SMEM), zfill sentinels.
__global__ __launch_bounds__(256, 2)
void gemm_bn_stats_kernel(const int* __restrict__ nb)
{
    extern __shared__ char smem[];
    __shared__ int   s_idx[2][128];
    __shared__ float s_sum[CDIM];
    __shared__ float s_sq[CDIM];

    const int t    = threadIdx.x;
    const int lane = t & 31;
    const int wid  = t >> 5;
    const int grp  = lane >> 2;
    const int tg   = lane & 3;
    const int m_base = (wid & 1) * 64;
    const int n_base = (wid >> 1) * 32;
    const int a    = blockIdx.y;
    const long i0  = (long)blockIdx.x * 128;
    const uint32_t sbase = smem_u32(smem);

    // producer mapping: A thread covers one row-half (2x16B), B one k-row pair
    const int pa_row = t >> 1;      // A: row 0..127
    const int pa_kh  = t & 1;       // which 16-half of the 32-k chunk
    const int pb_k   = t >> 3;      // B: k-row 0..31
    const int pb_nc  = t & 7;       // 16-half n-chunk pair

    if (t < CDIM) { s_sum[t] = 0.f; s_sq[t] = 0.f; }
    {   // gather indices for prev (si=0) / next (si=1)
        int si = t >> 7, r = t & 127;
        long gi = i0 + r;
        int v = NROWS;
        if (gi < NROWS) v = nb[((long)a * 2 + si) * NROWS + gi];
        s_idx[si][r] = v;
    }
    __syncthreads();

    const int swA = (pa_row >> 1) & 3;
    const int swB = pb_k & 7;

    auto issue = [&](int st) {
        const int s = st >> 2, kc = st & 3;
        const uint32_t Ab = sbase + (uint32_t)(st & 1) * BUF_SZ;
        const uint32_t Bb = Ab + A_TILE;
        long gi = i0 + pa_row;
        int ridx;
        if (s == 1) ridx = (gi < NROWS) ? (int)gi : NROWS;
        else        ridx = s_idx[s >> 1][pa_row];
        const bool ok = (ridx < NROWS);
        const __half* asrc = g_featH + (ok ? ((long)ridx * CDIM + kc * 32 + pa_kh * 16) : 0);
        uint32_t sz = ok ? 16u : 0u;
        uint32_t a0 = Ab + (uint32_t)pa_row * 64u + (uint32_t)((((pa_kh*2+0) ^ swA)) << 4);
        uint32_t a1 = Ab + (uint32_t)pa_row * 64u + (uint32_t)((((pa_kh*2+1) ^ swA)) << 4);
        CP_ASYNC16(a0, asrc,     sz);
        CP_ASYNC16(a1, asrc + 8, sz);
        const __half* bsrc = g_WH + ((long)(a * 3 + s) * CDIM + kc * 32 + pb_k) * CDIM + pb_nc * 16;
        uint32_t b0 = Bb + (uint32_t)pb_k * 256u + (uint32_t)((((pb_nc*2+0) ^ swB)) << 4);
        uint32_t b1 = Bb + (uint32_t)pb_k * 256u + (uint32_t)((((pb_nc*2+1) ^ swB)) << 4);
        CP_ASYNC16(b0, bsrc,     16u);
        CP_ASYNC16(b1, bsrc + 8, 16u);
    };

    issue(0); CP_COMMIT();
    issue(1); CP_COMMIT();

    float acc[4][4][4];
    #pragma unroll
    for (int i = 0; i < 4; i++)
        #pragma unroll
        for (int j = 0; j < 4; j++)
            #pragma unroll
            for (int q = 0; q < 4; q++) acc[i][j][q] = 0.f;

    const int l15 = lane & 15;
    const int lhi = lane >> 4;

    #pragma unroll 1
    for (int st = 0; st < 12; st++) {
        CP_WAIT1();          // group #st complete
        __syncthreads();

        const uint32_t Ab = sbase + (uint32_t)(st & 1) * BUF_SZ;
        const uint32_t Bb = Ab + A_TILE;

        #pragma unroll
        for (int ks = 0; ks < 2; ks++) {     // two k16-steps per 32-k stage
            uint32_t av[4][4];
            #pragma unroll
            for (int mt = 0; mt < 4; mt++) {
                int row = m_base + mt * 16 + l15;
                int ch  = 2 * ks + lhi;
                uint32_t ad = Ab + (uint32_t)row * 64u
                            + (uint32_t)(((ch ^ ((row >> 1) & 3))) << 4);
                LDSM_X4(av[mt], ad);
            }
            uint32_t bv[2][4];
            #pragma unroll
            for (int ntp = 0; ntp < 2; ntp++) {
                int k  = ks * 16 + l15;
                int ch = (n_base >> 3) + ntp * 2 + lhi;
                uint32_t bd = Bb + (uint32_t)k * 256u
                            + (uint32_t)(((ch ^ (k & 7))) << 4);
                LDSM_X4_T(bv[ntp], bd);
            }
            #pragma unroll
            for (int mt = 0; mt < 4; mt++)
                #pragma unroll
                for (int nt = 0; nt < 4; nt++)
                    MMA_F16(acc[mt][nt], av[mt], &bv[nt >> 1][(nt & 1) * 2]);
        }

        __syncthreads();     // all warps done reading buf before refilling it
        if (st + 2 < 12) issue(st + 2);
        CP_COMMIT();         // unconditional: keeps group numbering for CP_WAIT1
    }

    // ---- store tile to fp16 scratch + per-column fp32 stats ----
    const int vr = (int)(((NROWS - i0) < 128) ? (NROWS - i0) : 128);
    __half2* sc2 = (__half2*)(g_scratchH + ((long)a * NPAD + i0) * CDIM);

    #pragma unroll
    for (int nt = 0; nt < 4; nt++) {
        const int c_lo = n_base + nt * 8 + tg * 2;
        float sA = 0.f, qA = 0.f, sB = 0.f, qB = 0.f;
        #pragma unroll
        for (int mt = 0; mt < 4; mt++) {
            const int r0 = m_base + mt * 16 + grp;
            const int r1 = r0 + 8;
            sc2[((long)r0 * CDIM + c_lo) >> 1] = __floats2half2_rn(acc[mt][nt][0], acc[mt][nt][1]);
            sc2[((long)r1 * CDIM + c_lo) >> 1] = __floats2half2_rn(acc[mt][nt][2], acc[mt][nt][3]);
            if (r0 < vr) {
                float x = acc[mt][nt][0], y = acc[mt][nt][1];
                sA += x; qA += x * x; sB += y; qB += y * y;
            }
            if (r1 < vr) {
                float x = acc[mt][nt][2], y = acc[mt][nt][3];
                sA += x; qA += x * x; sB += y; qB += y * y;
            }
        }
        atomicAdd(&s_sum[c_lo],     sA); atomicAdd(&s_sq[c_lo],     qA);
        atomicAdd(&s_sum[c_lo + 1], sB); atomicAdd(&s_sq[c_lo + 1], qB);
    }
    __syncthreads();
    if (t < CDIM) {
        atomicAdd(&g_sum[a * CDIM + t],   s_sum[t]);
        atomicAdd(&g_sumsq[a * CDIM + t], s_sq[t]);
    }
}

__global__ void finalize_kernel(const float* __restrict__ gamma,
                                const float* __restrict__ beta)
{
    int t = blockIdx.x * blockDim.x + threadIdx.x;
    if (t >= 3 * CDIM) return;
    float inv_n = 1.0f / (float)NROWS;
    float mu  = g_sum[t] * inv_n;
    float var = g_sumsq[t] * inv_n - mu * mu;
    float sc  = gamma[t] * rsqrtf(var + EPS);
    g_scale[t] = sc;
    g_shift[t] = beta[t] - mu * sc;
}

__global__ __launch_bounds__(256)
void epilogue_kernel(const float* __restrict__ feat, float* __restrict__ out)
{
    long gid = (long)blockIdx.x * blockDim.x + threadIdx.x;   // one float4 each
    if (gid >= (long)NROWS * (CDIM / 4)) return;
    long i  = gid >> 5;
    int  c4 = ((int)gid & 31) << 2;

    float4 f = *(const float4*)(feat + i * CDIM + c4);
    float r0 = 0.f, r1 = 0.f, r2 = 0.f, r3 = 0.f;
    #pragma unroll
    for (int a = 0; a < 3; a++) {
        const __half2* sp = (const __half2*)(g_scratchH + ((long)a * NPAD + i) * CDIM + c4);
        float2 p0 = __half22float2(sp[0]);
        float2 p1 = __half22float2(sp[1]);
        float4 sc = *(const float4*)(g_scale + a * CDIM + c4);
        float4 sh = *(const float4*)(g_shift + a * CDIM + c4);
        r0 += 1.f / (1.f + __expf(-(p0.x * sc.x + sh.x)));
        r1 += 1.f / (1.f + __expf(-(p0.y * sc.y + sh.y)));
        r2 += 1.f / (1.f + __expf(-(p1.x * sc.z + sh.z)));
        r3 += 1.f / (1.f + __expf(-(p1.y * sc.w + sh.w)));
    }
    float4 o = make_float4(r0 * f.x, r1 * f.y, r2 * f.z, r3 * f.w);
    *(float4*)(out + i * CDIM + c4) = o;
}

extern "C" void kernel_launch(void* const* d_in, const int* in_sizes, int n_in,
                              void* d_out, int out_size)
{
    const float* feat  = (const float*)d_in[0];
    const int*   nb    = (const int*)  d_in[1];
    const float* W     = (const float*)d_in[2];
    const float* gamma = (const float*)d_in[3];
    const float* beta  = (const float*)d_in[4];
    float*       out   = (float*)d_out;

    cudaFuncSetAttribute(gemm_bn_stats_kernel,
                         cudaFuncAttributeMaxDynamicSharedMemorySize, SMEM_DYN);

    zero_stats_kernel<<<2, 256>>>();
    convert_feat_kernel<<<12500, 256>>>(feat);
    convert_w_kernel<<<72, 256>>>(W);
    dim3 g(NPAD / 128, 3);
    gemm_bn_stats_kernel<<<g, 256, SMEM_DYN>>>(nb);
    finalize_kernel<<<2, 256>>>(gamma, beta);
    epilogue_kernel<<<25000, 256>>>(feat, out);
}